// round 7
// baseline (speedup 1.0000x reference)
#include <cuda_runtime.h>
#include <cuda_bf16.h>
#include <math.h>
#include <stdint.h>

#define Bn 64
#define Hn 512
#define En 256
#define Vn 32000
#define Sn 64
#define NVB 250       /* Vn / 128 v-blocks in logits kernel */
#define NKT 32        /* logits k-tiles of 16 (Hn/16) */
#define GKT 48        /* gates  k-tiles of 16 ((En+Hn)/16) */

// ---------------- persistent device state (no cudaMalloc allowed) ------------
__device__ float g_c[Bn * Hn];
__device__ float g_pval[Bn * NVB];
__device__ int   g_pidx[Bn * NVB];
__device__ int   g_tf[Sn];

// logits W fragments: [mtile(2000)][ktile(32)][lane(32)][8 bf16]
__device__ __nv_bfloat16 g_wfrag_hi[(size_t)Vn * Hn];
__device__ __nv_bfloat16 g_wfrag_lo[(size_t)Vn * Hn];
// gates W fragments: [cta(16)*8 + mtile][ktile(48)][lane(32)][8 bf16]
__device__ __nv_bfloat16 g_wg_hi[(size_t)128 * GKT * 32 * 8];
__device__ __nv_bfloat16 g_wg_lo[(size_t)128 * GKT * 32 * 8];
// h B-fragments, double buffered: [buf][ntile(8)][ktile(32)][lane(32)][4 bf16]
__device__ __nv_bfloat16 g_hfrag_hi[2][Bn * Hn];
__device__ __nv_bfloat16 g_hfrag_lo[2][Bn * Hn];
// x B-fragments: [ntile(8)][ktile(16)][lane(32)][4 bf16]
__device__ __nv_bfloat16 g_xfrag_hi[Bn * En];
__device__ __nv_bfloat16 g_xfrag_lo[Bn * En];

__device__ __forceinline__ float sigmoidf_(float x) {
    return 1.0f / (1.0f + expf(-x));
}

__device__ __forceinline__ void mma16816(float* c, const uint4& a, const uint2& b) {
    asm volatile(
        "mma.sync.aligned.m16n8k16.row.col.f32.bf16.bf16.f32 "
        "{%0,%1,%2,%3}, {%4,%5,%6,%7}, {%8,%9}, {%0,%1,%2,%3};"
        : "+f"(c[0]), "+f"(c[1]), "+f"(c[2]), "+f"(c[3])
        : "r"(a.x), "r"(a.y), "r"(a.z), "r"(a.w), "r"(b.x), "r"(b.y));
}

// ---------------- one-time conversions ---------------------------------------
__global__ void convert_w_kernel(const float* __restrict__ fc_w) {
    size_t idx = (size_t)blockIdx.x * blockDim.x + threadIdx.x;
    if (idx >= (size_t)Vn * Hn) return;
    int v = (int)(idx >> 9);
    int kg = (int)(idx & 511);
    float w = fc_w[idx];
    __nv_bfloat16 hi = __float2bfloat16(w);
    __nv_bfloat16 lo = __float2bfloat16(w - __bfloat162float(hi));
    int mtile = v >> 4, r = v & 15;
    int ktile = kg >> 4, c = kg & 15;
    int lane = (r & 7) * 4 + ((c & 7) >> 1);
    int reg  = (r >> 3) + 2 * (c >> 3);
    int pos  = c & 1;
    size_t off = ((size_t)(mtile * NKT + ktile) * 32 + lane) * 8 + reg * 2 + pos;
    g_wfrag_hi[off] = hi;
    g_wfrag_lo[off] = lo;
}

__global__ void convert_wg_kernel(const float* __restrict__ W_ih,
                                  const float* __restrict__ W_hh) {
    size_t idx = (size_t)blockIdx.x * blockDim.x + threadIdx.x;
    if (idx >= (size_t)2048 * 768) return;
    int R = (int)(idx / 768);
    int kc = (int)(idx % 768);
    float w = (kc < En) ? W_ih[(size_t)R * En + kc]
                        : W_hh[(size_t)R * Hn + (kc - En)];
    __nv_bfloat16 hi = __float2bfloat16(w);
    __nv_bfloat16 lo = __float2bfloat16(w - __bfloat162float(hi));
    int gate = R >> 9, j = R & 511;
    int bid = j >> 5;
    int rloc = gate * 32 + (j & 31);        // 0..127
    int mtile = bid * 8 + (rloc >> 4);
    int r16 = rloc & 15;
    int ktile = kc >> 4, c = kc & 15;
    int lane = (r16 & 7) * 4 + ((c & 7) >> 1);
    int reg  = (r16 >> 3) + 2 * (c >> 3);
    int pos  = c & 1;
    size_t off = ((size_t)(mtile * GKT + ktile) * 32 + lane) * 8 + reg * 2 + pos;
    g_wg_hi[off] = hi;
    g_wg_lo[off] = lo;
}

// ---------------- init: decode use_tf, zero out[:,0,:] -----------------------
__global__ void init_kernel(const unsigned char* tf_raw, float* out) {
    if (blockIdx.x == 0) {
        __shared__ int mode;
        if (threadIdx.x == 0) {
            int gt1 = 0, odd1 = 0;
            for (int i = 0; i < Sn; i++) {
                unsigned char v = tf_raw[i];
                if (v > 1) gt1 = 1;
                if (v == 1 && (i & 3)) odd1 = 1;
            }
            mode = gt1 ? 1 : (odd1 ? 0 : 1);
        }
        __syncthreads();
        if (threadIdx.x < Sn) {
            int t = threadIdx.x;
            int val;
            if (mode == 0) val = (tf_raw[t] != 0);
            else           val = (((const unsigned int*)tf_raw)[t] != 0u);
            g_tf[t] = val;
        }
    }
    for (int i = blockIdx.x * blockDim.x + threadIdx.x; i < Bn * Vn;
         i += gridDim.x * blockDim.x) {
        int b = i / Vn, v = i - b * Vn;
        out[(size_t)b * Sn * Vn + v] = 0.0f;
    }
}

// ---------------- prep: resolve tokens, emit x-frags (k=0: h-frags too) ------
__global__ __launch_bounds__(256) void prep_kernel(
    int k, const int* __restrict__ captions, const float* __restrict__ emb,
    const float* __restrict__ enc)
{
    __shared__ int tok_s[Bn];
    int tid = threadIdx.x;

    if (k == 0) {
        if (tid < Bn) tok_s[tid] = captions[tid * Sn + 0];
    } else {
        int b = tid >> 2, l4 = tid & 3;
        float bv = -3.4e38f; int bi = 0x7fffffff;
        for (int p = l4; p < NVB; p += 4) {
            float v = g_pval[b * NVB + p];
            int  ii = g_pidx[b * NVB + p];
            if (v > bv || (v == bv && ii < bi)) { bv = v; bi = ii; }
        }
        #pragma unroll
        for (int off = 2; off > 0; off >>= 1) {
            float ov = __shfl_down_sync(0xffffffffu, bv, off, 4);
            int   oi = __shfl_down_sync(0xffffffffu, bi, off, 4);
            if (ov > bv || (ov == bv && oi < bi)) { bv = ov; bi = oi; }
        }
        if (l4 == 0)
            tok_s[b] = g_tf[k] ? captions[b * Sn + k] : bi;
    }
    __syncthreads();

    // x fragments: 64 b x 256 dims
    for (int e = tid; e < Bn * En; e += 256) {
        int b = e >> 8, kg = e & 255;
        int tok = tok_s[b];
        float x = (tok == 0) ? 0.0f : emb[(size_t)tok * En + kg];
        __nv_bfloat16 hi = __float2bfloat16(x);
        __nv_bfloat16 lo = __float2bfloat16(x - __bfloat162float(hi));
        int ntile = b >> 3, n = b & 7;
        int ktile = kg >> 4, c = kg & 15;
        int lane = n * 4 + ((c & 7) >> 1);
        int reg  = c >> 3, pos = c & 1;
        uint32_t off = ((uint32_t)(ntile * 16 + ktile) * 32 + lane) * 4 + reg * 2 + pos;
        g_xfrag_hi[off] = hi;
        g_xfrag_lo[off] = lo;
    }

    // k=0: h fragments from encoder_hidden into buffer 0
    if (k == 0) {
        for (int e = tid; e < Bn * Hn; e += 256) {
            int b = e >> 9, j = e & 511;
            float h = enc[b * Hn + j];
            __nv_bfloat16 hi = __float2bfloat16(h);
            __nv_bfloat16 lo = __float2bfloat16(h - __bfloat162float(hi));
            int ntile = b >> 3, n = b & 7;
            int ktile = j >> 4, c = j & 15;
            int lane = n * 4 + ((c & 7) >> 1);
            int reg  = c >> 3, pos = c & 1;
            uint32_t off = ((uint32_t)(ntile * NKT + ktile) * 32 + lane) * 4 + reg * 2 + pos;
            g_hfrag_hi[0][off] = hi;
            g_hfrag_lo[0][off] = lo;
        }
    }
}

// ---------------- fused gates MMA + cell update -------------------------------
// grid 16 x 256. CTA bid: j-range [bid*32, +32) x all 4 gates (128 rows), K=768.
__global__ __launch_bounds__(256) void gatescell_kernel(
    int k, const float* __restrict__ b_ih, const float* __restrict__ b_hh)
{
    __shared__ float s_g[128][66];

    int tid = threadIdx.x;
    int wid = tid >> 5, lane = tid & 31;
    int mw = wid & 3, nw = wid >> 2;
    int gid = lane >> 2, tig = lane & 3;
    int bid = blockIdx.x;
    int rb = k & 1, wb = (k + 1) & 1;

    const uint4* wh4 = (const uint4*)g_wg_hi;
    const uint4* wl4 = (const uint4*)g_wg_lo;
    const uint2* xh2 = (const uint2*)g_xfrag_hi;
    const uint2* xl2 = (const uint2*)g_xfrag_lo;
    const uint2* hh2 = (const uint2*)g_hfrag_hi[rb];
    const uint2* hl2 = (const uint2*)g_hfrag_lo[rb];

    float acc[2][4][4];
    #pragma unroll
    for (int mt = 0; mt < 2; mt++)
        #pragma unroll
        for (int nt = 0; nt < 4; nt++)
            #pragma unroll
            for (int i = 0; i < 4; i++) acc[mt][nt][i] = 0.0f;

    int mt_g0 = bid * 8 + mw * 2;

    for (int kt = 0; kt < GKT; kt++) {
        uint4 ahi[2], alo[2];
        #pragma unroll
        for (int mt = 0; mt < 2; mt++) {
            size_t base = ((size_t)(mt_g0 + mt) * GKT + kt) * 32 + lane;
            ahi[mt] = wh4[base];
            alo[mt] = wl4[base];
        }
        #pragma unroll
        for (int nt = 0; nt < 4; nt++) {
            int nt_g = nw * 4 + nt;
            uint2 bhi, blo;
            if (kt < 16) {
                uint32_t bbase = (uint32_t)(nt_g * 16 + kt) * 32 + lane;
                bhi = xh2[bbase]; blo = xl2[bbase];
            } else {
                uint32_t bbase = (uint32_t)(nt_g * NKT + (kt - 16)) * 32 + lane;
                bhi = hh2[bbase]; blo = hl2[bbase];
            }
            #pragma unroll
            for (int mt = 0; mt < 2; mt++) {
                mma16816(acc[mt][nt], ahi[mt], bhi);
                mma16816(acc[mt][nt], ahi[mt], blo);
                mma16816(acc[mt][nt], alo[mt], bhi);
            }
        }
    }

    // accumulators -> smem [row_local][b]
    #pragma unroll
    for (int mt = 0; mt < 2; mt++) {
        int rl = mw * 32 + mt * 16 + gid;
        #pragma unroll
        for (int nt = 0; nt < 4; nt++) {
            int bl = (nw * 4 + nt) * 8 + tig * 2;
            s_g[rl][bl]         = acc[mt][nt][0];
            s_g[rl][bl + 1]     = acc[mt][nt][1];
            s_g[rl + 8][bl]     = acc[mt][nt][2];
            s_g[rl + 8][bl + 1] = acc[mt][nt][3];
        }
    }
    __syncthreads();

    // cell update: 32 j x 64 b = 2048 elems, 8 per thread
    #pragma unroll
    for (int it = 0; it < 8; it++) {
        int e = tid + it * 256;
        int jl = e >> 6, b = e & 63;
        int j = bid * 32 + jl;

        float gi = s_g[jl][b]      + b_ih[j]            + b_hh[j];
        float gf = s_g[32 + jl][b] + b_ih[Hn + j]       + b_hh[Hn + j];
        float gg = s_g[64 + jl][b] + b_ih[2 * Hn + j]   + b_hh[2 * Hn + j];
        float go = s_g[96 + jl][b] + b_ih[3 * Hn + j]   + b_hh[3 * Hn + j];

        float c_old = (k == 0) ? 0.0f : g_c[b * Hn + j];
        float c = sigmoidf_(gf) * c_old + sigmoidf_(gi) * tanhf(gg);
        float h = sigmoidf_(go) * tanhf(c);
        g_c[b * Hn + j] = c;

        __nv_bfloat16 hi = __float2bfloat16(h);
        __nv_bfloat16 lo = __float2bfloat16(h - __bfloat162float(hi));
        int ntile = b >> 3, n = b & 7;
        int ktile = j >> 4, c2 = j & 15;
        int lane2 = n * 4 + ((c2 & 7) >> 1);
        int reg  = c2 >> 3, pos = c2 & 1;
        uint32_t off = ((uint32_t)(ntile * NKT + ktile) * 32 + lane2) * 4 + reg * 2 + pos;
        g_hfrag_hi[wb][off] = hi;
        g_hfrag_lo[wb][off] = lo;
    }
}

// ---------------- logits GEMM via mma.sync bf16 (3-term split) ---------------
__global__ __launch_bounds__(256) void logits_mma_kernel(
    int k, const float* __restrict__ fc_b, float* __restrict__ out)
{
    __shared__ float s_out[Bn][132];

    int tid = threadIdx.x;
    int wid = tid >> 5, lane = tid & 31;
    int mw = wid & 3, nw = wid >> 2;
    int gid = lane >> 2, tig = lane & 3;
    int wb = (k + 1) & 1;

    const uint4* wh4 = (const uint4*)g_wfrag_hi;
    const uint4* wl4 = (const uint4*)g_wfrag_lo;
    const uint2* hh2 = (const uint2*)g_hfrag_hi[wb];
    const uint2* hl2 = (const uint2*)g_hfrag_lo[wb];

    int mt_g0 = blockIdx.x * 8 + mw * 2;

    float acc[2][4][4];
    #pragma unroll
    for (int mt = 0; mt < 2; mt++)
        #pragma unroll
        for (int nt = 0; nt < 4; nt++)
            #pragma unroll
            for (int i = 0; i < 4; i++) acc[mt][nt][i] = 0.0f;

    for (int kt = 0; kt < NKT; kt++) {
        uint4 ahi[2], alo[2];
        #pragma unroll
        for (int mt = 0; mt < 2; mt++) {
            size_t base = ((size_t)(mt_g0 + mt) * NKT + kt) * 32 + lane;
            ahi[mt] = wh4[base];
            alo[mt] = wl4[base];
        }
        #pragma unroll
        for (int nt = 0; nt < 4; nt++) {
            int nt_g = nw * 4 + nt;
            uint32_t bbase = (uint32_t)(nt_g * NKT + kt) * 32 + lane;
            uint2 bhi = hh2[bbase];
            uint2 blo = hl2[bbase];
            #pragma unroll
            for (int mt = 0; mt < 2; mt++) {
                mma16816(acc[mt][nt], ahi[mt], bhi);
                mma16816(acc[mt][nt], ahi[mt], blo);
                mma16816(acc[mt][nt], alo[mt], bhi);
            }
        }
    }

    #pragma unroll
    for (int mt = 0; mt < 2; mt++) {
        int vl = mw * 32 + mt * 16 + gid;
        #pragma unroll
        for (int nt = 0; nt < 4; nt++) {
            int bl = (nw * 4 + nt) * 8 + tig * 2;
            s_out[bl][vl]         = acc[mt][nt][0];
            s_out[bl + 1][vl]     = acc[mt][nt][1];
            s_out[bl][vl + 8]     = acc[mt][nt][2];
            s_out[bl + 1][vl + 8] = acc[mt][nt][3];
        }
    }
    __syncthreads();

    int v0g = blockIdx.x * 128;
    int t = k + 1;
    int b = tid >> 2, q = tid & 3;
    float* orow = out + ((size_t)b * Sn + t) * Vn + v0g + q * 32;
    float bv = -3.4e38f; int bi = 0x7fffffff;
    #pragma unroll
    for (int g8 = 0; g8 < 8; g8++) {
        float4 r;
        float* sp = &s_out[b][q * 32 + g8 * 4];
        const float* bp = fc_b + v0g + q * 32 + g8 * 4;
        r.x = sp[0] + bp[0];
        r.y = sp[1] + bp[1];
        r.z = sp[2] + bp[2];
        r.w = sp[3] + bp[3];
        *(float4*)(orow + g8 * 4) = r;
        int vb = v0g + q * 32 + g8 * 4;
        if (r.x > bv) { bv = r.x; bi = vb; }
        if (r.y > bv) { bv = r.y; bi = vb + 1; }
        if (r.z > bv) { bv = r.z; bi = vb + 2; }
        if (r.w > bv) { bv = r.w; bi = vb + 3; }
    }
    #pragma unroll
    for (int off = 2; off > 0; off >>= 1) {
        float ov = __shfl_down_sync(0xffffffffu, bv, off, 4);
        int   oi = __shfl_down_sync(0xffffffffu, bi, off, 4);
        if (ov > bv || (ov == bv && oi < bi)) { bv = ov; bi = oi; }
    }
    if (q == 0) {
        g_pval[b * NVB + blockIdx.x] = bv;
        g_pidx[b * NVB + blockIdx.x] = bi;
    }
}

// ---------------- launch ------------------------------------------------------
extern "C" void kernel_launch(void* const* d_in, const int* in_sizes, int n_in,
                              void* d_out, int out_size) {
    (void)in_sizes; (void)n_in; (void)out_size;
    const float*         enc  = (const float*)d_in[0];
    const int*           caps = (const int*)d_in[1];
    const unsigned char* tf   = (const unsigned char*)d_in[2];
    const float*         emb  = (const float*)d_in[3];
    const float*         W_ih = (const float*)d_in[4];
    const float*         W_hh = (const float*)d_in[5];
    const float*         b_ih = (const float*)d_in[6];
    const float*         b_hh = (const float*)d_in[7];
    const float*         fc_w = (const float*)d_in[8];
    const float*         fc_b = (const float*)d_in[9];
    float* out = (float*)d_out;

    init_kernel<<<512, 256>>>(tf, out);
    convert_w_kernel<<<(Vn * Hn + 255) / 256, 256>>>(fc_w);
    convert_wg_kernel<<<(2048 * 768 + 255) / 256, 256>>>(W_ih, W_hh);
    for (int k = 0; k < 63; k++) {
        prep_kernel<<<1, 256>>>(k, caps, emb, enc);
        gatescell_kernel<<<16, 256>>>(k, b_ih, b_hh);
        logits_mma_kernel<<<250, 256>>>(k, fc_b, out);
    }
}

// round 10
// speedup vs baseline: 1.2584x; 1.2584x over previous
#include <cuda_runtime.h>
#include <cuda_bf16.h>
#include <math.h>
#include <stdint.h>

#define Bn 64
#define Hn 512
#define En 256
#define Vn 32000
#define Sn 64
#define NVB 250       /* Vn / 128 v-blocks in logits kernel */
#define NKT 32        /* logits k-tiles of 16 (Hn/16) */
#define GKT 48        /* gates  k-tiles of 16 ((En+Hn)/16) */

// ---------------- persistent device state (no cudaMalloc allowed) ------------
__device__ float g_c[Bn * Hn];
__device__ float g_pval[Bn * NVB];
__device__ int   g_pidx[Bn * NVB];
__device__ int   g_tf[Sn];

// logits W fragments: [mtile(2000)][ktile(32)][lane(32)][8 bf16]
__device__ __nv_bfloat16 g_wfrag_hi[(size_t)Vn * Hn];
__device__ __nv_bfloat16 g_wfrag_lo[(size_t)Vn * Hn];
// gates W fragments: [cta(16)*8 + mtile][ktile(48)][lane(32)][8 bf16]
__device__ __nv_bfloat16 g_wg_hi[(size_t)128 * GKT * 32 * 8];
__device__ __nv_bfloat16 g_wg_lo[(size_t)128 * GKT * 32 * 8];
// h B-fragments, double buffered: [buf][ntile(8)][ktile(32)][lane(32)][4 bf16]
__device__ __nv_bfloat16 g_hfrag_hi[2][Bn * Hn];
__device__ __nv_bfloat16 g_hfrag_lo[2][Bn * Hn];
// x B-fragments: [ntile(8)][ktile(16)][lane(32)][4 bf16]
__device__ __nv_bfloat16 g_xfrag_hi[Bn * En];
__device__ __nv_bfloat16 g_xfrag_lo[Bn * En];

__device__ __forceinline__ float sigmoidf_(float x) {
    return 1.0f / (1.0f + expf(-x));
}

__device__ __forceinline__ void mma16816(float* c, const uint4& a, const uint2& b) {
    asm volatile(
        "mma.sync.aligned.m16n8k16.row.col.f32.bf16.bf16.f32 "
        "{%0,%1,%2,%3}, {%4,%5,%6,%7}, {%8,%9}, {%0,%1,%2,%3};"
        : "+f"(c[0]), "+f"(c[1]), "+f"(c[2]), "+f"(c[3])
        : "r"(a.x), "r"(a.y), "r"(a.z), "r"(a.w), "r"(b.x), "r"(b.y));
}

// ---------------- one-time conversions ---------------------------------------
__global__ void convert_w_kernel(const float* __restrict__ fc_w) {
    size_t idx = (size_t)blockIdx.x * blockDim.x + threadIdx.x;
    if (idx >= (size_t)Vn * Hn) return;
    int v = (int)(idx >> 9);
    int kg = (int)(idx & 511);
    float w = fc_w[idx];
    __nv_bfloat16 hi = __float2bfloat16(w);
    __nv_bfloat16 lo = __float2bfloat16(w - __bfloat162float(hi));
    int mtile = v >> 4, r = v & 15;
    int ktile = kg >> 4, c = kg & 15;
    int lane = (r & 7) * 4 + ((c & 7) >> 1);
    int reg  = (r >> 3) + 2 * (c >> 3);
    int pos  = c & 1;
    size_t off = ((size_t)(mtile * NKT + ktile) * 32 + lane) * 8 + reg * 2 + pos;
    g_wfrag_hi[off] = hi;
    g_wfrag_lo[off] = lo;
}

__global__ void convert_wg_kernel(const float* __restrict__ W_ih,
                                  const float* __restrict__ W_hh) {
    size_t idx = (size_t)blockIdx.x * blockDim.x + threadIdx.x;
    if (idx >= (size_t)2048 * 768) return;
    int R = (int)(idx / 768);
    int kc = (int)(idx % 768);
    float w = (kc < En) ? W_ih[(size_t)R * En + kc]
                        : W_hh[(size_t)R * Hn + (kc - En)];
    __nv_bfloat16 hi = __float2bfloat16(w);
    __nv_bfloat16 lo = __float2bfloat16(w - __bfloat162float(hi));
    int gate = R >> 9, j = R & 511;
    int bid = j >> 5;
    int rloc = gate * 32 + (j & 31);        // 0..127
    int mtile = bid * 8 + (rloc >> 4);
    int r16 = rloc & 15;
    int ktile = kc >> 4, c = kc & 15;
    int lane = (r16 & 7) * 4 + ((c & 7) >> 1);
    int reg  = (r16 >> 3) + 2 * (c >> 3);
    int pos  = c & 1;
    size_t off = ((size_t)(mtile * GKT + ktile) * 32 + lane) * 8 + reg * 2 + pos;
    g_wg_hi[off] = hi;
    g_wg_lo[off] = lo;
}

// ---------------- init: decode use_tf, zero out[:,0,:] -----------------------
__global__ void init_kernel(const unsigned char* tf_raw, float* out) {
    if (blockIdx.x == 0) {
        __shared__ int mode;
        if (threadIdx.x == 0) {
            int gt1 = 0, odd1 = 0;
            for (int i = 0; i < Sn; i++) {
                unsigned char v = tf_raw[i];
                if (v > 1) gt1 = 1;
                if (v == 1 && (i & 3)) odd1 = 1;
            }
            mode = gt1 ? 1 : (odd1 ? 0 : 1);
        }
        __syncthreads();
        if (threadIdx.x < Sn) {
            int t = threadIdx.x;
            int val;
            if (mode == 0) val = (tf_raw[t] != 0);
            else           val = (((const unsigned int*)tf_raw)[t] != 0u);
            g_tf[t] = val;
        }
    }
    for (int i = blockIdx.x * blockDim.x + threadIdx.x; i < Bn * Vn;
         i += gridDim.x * blockDim.x) {
        int b = i / Vn, v = i - b * Vn;
        out[(size_t)b * Sn * Vn + v] = 0.0f;
    }
}

// ---------------- prep: grid 64 (one CTA per batch lane) ----------------------
// Resolve token (parallel argmax over 250 partials), emit x-frags;
// k=0: also emit h-frags from encoder_hidden.
__global__ __launch_bounds__(256) void prep_kernel(
    int k, const int* __restrict__ captions, const float* __restrict__ emb,
    const float* __restrict__ enc)
{
    __shared__ float sval[8];
    __shared__ int   sidx[8];
    __shared__ int   tok_sh;

    int b = blockIdx.x;
    int tid = threadIdx.x;
    int lane = tid & 31, warp = tid >> 5;

    if (k == 0) {
        if (tid == 0) tok_sh = captions[b * Sn + 0];
    } else {
        float bv = -3.4e38f; int bi = 0x7fffffff;
        if (tid < NVB) { bv = g_pval[b * NVB + tid]; bi = g_pidx[b * NVB + tid]; }
        #pragma unroll
        for (int off = 16; off > 0; off >>= 1) {
            float ov = __shfl_down_sync(0xffffffffu, bv, off);
            int   oi = __shfl_down_sync(0xffffffffu, bi, off);
            if (ov > bv || (ov == bv && oi < bi)) { bv = ov; bi = oi; }
        }
        if (lane == 0) { sval[warp] = bv; sidx[warp] = bi; }
        __syncthreads();
        if (tid == 0) {
            bv = sval[0]; bi = sidx[0];
            #pragma unroll
            for (int w2 = 1; w2 < 8; w2++) {
                float ov = sval[w2]; int oi = sidx[w2];
                if (ov > bv || (ov == bv && oi < bi)) { bv = ov; bi = oi; }
            }
            tok_sh = g_tf[k] ? captions[b * Sn + k] : bi;
        }
    }
    __syncthreads();

    int tok = tok_sh;
    // x fragments: this lane's 256 dims, one per thread
    {
        int kg = tid;
        float x = (tok == 0) ? 0.0f : emb[(size_t)tok * En + kg];
        __nv_bfloat16 hi = __float2bfloat16(x);
        __nv_bfloat16 lo = __float2bfloat16(x - __bfloat162float(hi));
        int ntile = b >> 3, n = b & 7;
        int ktile = kg >> 4, c = kg & 15;
        int lane2 = n * 4 + ((c & 7) >> 1);
        int reg  = c >> 3, pos = c & 1;
        uint32_t off = ((uint32_t)(ntile * 16 + ktile) * 32 + lane2) * 4 + reg * 2 + pos;
        g_xfrag_hi[off] = hi;
        g_xfrag_lo[off] = lo;
    }

    // k=0: h fragments from encoder_hidden into buffer 0 (512 dims, 2/thread)
    if (k == 0) {
        #pragma unroll
        for (int q = 0; q < 2; q++) {
            int j = tid + q * 256;
            float h = enc[b * Hn + j];
            __nv_bfloat16 hi = __float2bfloat16(h);
            __nv_bfloat16 lo = __float2bfloat16(h - __bfloat162float(hi));
            int ntile = b >> 3, n = b & 7;
            int ktile = j >> 4, c = j & 15;
            int lane2 = n * 4 + ((c & 7) >> 1);
            int reg  = c >> 3, pos = c & 1;
            uint32_t off = ((uint32_t)(ntile * NKT + ktile) * 32 + lane2) * 4 + reg * 2 + pos;
            g_hfrag_hi[0][off] = hi;
            g_hfrag_lo[0][off] = lo;
        }
    }
}

// ---------------- fused gates MMA + cell update -------------------------------
// grid 16 x 256. CTA bid: j-range [bid*32, +32) x all 4 gates (128 rows), K=768.
__global__ __launch_bounds__(256) void gatescell_kernel(
    int k, const float* __restrict__ b_ih, const float* __restrict__ b_hh)
{
    __shared__ float s_g[128][66];

    int tid = threadIdx.x;
    int wid = tid >> 5, lane = tid & 31;
    int mw = wid & 3, nw = wid >> 2;
    int gid = lane >> 2, tig = lane & 3;
    int bid = blockIdx.x;
    int rb = k & 1, wb = (k + 1) & 1;

    const uint4* wh4 = (const uint4*)g_wg_hi;
    const uint4* wl4 = (const uint4*)g_wg_lo;
    const uint2* xh2 = (const uint2*)g_xfrag_hi;
    const uint2* xl2 = (const uint2*)g_xfrag_lo;
    const uint2* hh2 = (const uint2*)g_hfrag_hi[rb];
    const uint2* hl2 = (const uint2*)g_hfrag_lo[rb];

    float acc[2][4][4];
    #pragma unroll
    for (int mt = 0; mt < 2; mt++)
        #pragma unroll
        for (int nt = 0; nt < 4; nt++)
            #pragma unroll
            for (int i = 0; i < 4; i++) acc[mt][nt][i] = 0.0f;

    int mt_g0 = bid * 8 + mw * 2;

    for (int kt = 0; kt < GKT; kt++) {
        uint4 ahi[2], alo[2];
        #pragma unroll
        for (int mt = 0; mt < 2; mt++) {
            size_t base = ((size_t)(mt_g0 + mt) * GKT + kt) * 32 + lane;
            ahi[mt] = wh4[base];
            alo[mt] = wl4[base];
        }
        #pragma unroll
        for (int nt = 0; nt < 4; nt++) {
            int nt_g = nw * 4 + nt;
            uint2 bhi, blo;
            if (kt < 16) {
                uint32_t bbase = (uint32_t)(nt_g * 16 + kt) * 32 + lane;
                bhi = xh2[bbase]; blo = xl2[bbase];
            } else {
                uint32_t bbase = (uint32_t)(nt_g * NKT + (kt - 16)) * 32 + lane;
                bhi = hh2[bbase]; blo = hl2[bbase];
            }
            #pragma unroll
            for (int mt = 0; mt < 2; mt++) {
                mma16816(acc[mt][nt], ahi[mt], bhi);
                mma16816(acc[mt][nt], ahi[mt], blo);
                mma16816(acc[mt][nt], alo[mt], bhi);
            }
        }
    }

    // accumulators -> smem [row_local][b]
    #pragma unroll
    for (int mt = 0; mt < 2; mt++) {
        int rl = mw * 32 + mt * 16 + gid;
        #pragma unroll
        for (int nt = 0; nt < 4; nt++) {
            int bl = (nw * 4 + nt) * 8 + tig * 2;
            s_g[rl][bl]         = acc[mt][nt][0];
            s_g[rl][bl + 1]     = acc[mt][nt][1];
            s_g[rl + 8][bl]     = acc[mt][nt][2];
            s_g[rl + 8][bl + 1] = acc[mt][nt][3];
        }
    }
    __syncthreads();

    // cell update: 32 j x 64 b = 2048 elems, 8 per thread
    #pragma unroll
    for (int it = 0; it < 8; it++) {
        int e = tid + it * 256;
        int jl = e >> 6, b = e & 63;
        int j = bid * 32 + jl;

        float gi = s_g[jl][b]      + b_ih[j]            + b_hh[j];
        float gf = s_g[32 + jl][b] + b_ih[Hn + j]       + b_hh[Hn + j];
        float gg = s_g[64 + jl][b] + b_ih[2 * Hn + j]   + b_hh[2 * Hn + j];
        float go = s_g[96 + jl][b] + b_ih[3 * Hn + j]   + b_hh[3 * Hn + j];

        float c_old = (k == 0) ? 0.0f : g_c[b * Hn + j];
        float c = sigmoidf_(gf) * c_old + sigmoidf_(gi) * tanhf(gg);
        float h = sigmoidf_(go) * tanhf(c);
        g_c[b * Hn + j] = c;

        __nv_bfloat16 hi = __float2bfloat16(h);
        __nv_bfloat16 lo = __float2bfloat16(h - __bfloat162float(hi));
        int ntile = b >> 3, n = b & 7;
        int ktile = j >> 4, c2 = j & 15;
        int lane2 = n * 4 + ((c2 & 7) >> 1);
        int reg  = c2 >> 3, pos = c2 & 1;
        uint32_t off = ((uint32_t)(ntile * NKT + ktile) * 32 + lane2) * 4 + reg * 2 + pos;
        g_hfrag_hi[wb][off] = hi;
        g_hfrag_lo[wb][off] = lo;
    }
}

// ---------------- logits GEMM via mma.sync bf16 (3-term split) ---------------
__global__ __launch_bounds__(256) void logits_mma_kernel(
    int k, const float* __restrict__ fc_b, float* __restrict__ out)
{
    __shared__ float s_out[Bn][132];

    int tid = threadIdx.x;
    int wid = tid >> 5, lane = tid & 31;
    int mw = wid & 3, nw = wid >> 2;
    int gid = lane >> 2, tig = lane & 3;
    int wb = (k + 1) & 1;

    const uint4* wh4 = (const uint4*)g_wfrag_hi;
    const uint4* wl4 = (const uint4*)g_wfrag_lo;
    const uint2* hh2 = (const uint2*)g_hfrag_hi[wb];
    const uint2* hl2 = (const uint2*)g_hfrag_lo[wb];

    int mt_g0 = blockIdx.x * 8 + mw * 2;

    float acc[2][4][4];
    #pragma unroll
    for (int mt = 0; mt < 2; mt++)
        #pragma unroll
        for (int nt = 0; nt < 4; nt++)
            #pragma unroll
            for (int i = 0; i < 4; i++) acc[mt][nt][i] = 0.0f;

    for (int kt = 0; kt < NKT; kt++) {
        uint4 ahi[2], alo[2];
        #pragma unroll
        for (int mt = 0; mt < 2; mt++) {
            size_t base = ((size_t)(mt_g0 + mt) * NKT + kt) * 32 + lane;
            ahi[mt] = wh4[base];
            alo[mt] = wl4[base];
        }
        #pragma unroll
        for (int nt = 0; nt < 4; nt++) {
            int nt_g = nw * 4 + nt;
            uint32_t bbase = (uint32_t)(nt_g * NKT + kt) * 32 + lane;
            uint2 bhi = hh2[bbase];
            uint2 blo = hl2[bbase];
            #pragma unroll
            for (int mt = 0; mt < 2; mt++) {
                mma16816(acc[mt][nt], ahi[mt], bhi);
                mma16816(acc[mt][nt], ahi[mt], blo);
                mma16816(acc[mt][nt], alo[mt], bhi);
            }
        }
    }

    #pragma unroll
    for (int mt = 0; mt < 2; mt++) {
        int vl = mw * 32 + mt * 16 + gid;
        #pragma unroll
        for (int nt = 0; nt < 4; nt++) {
            int bl = (nw * 4 + nt) * 8 + tig * 2;
            s_out[bl][vl]         = acc[mt][nt][0];
            s_out[bl + 1][vl]     = acc[mt][nt][1];
            s_out[bl][vl + 8]     = acc[mt][nt][2];
            s_out[bl + 1][vl + 8] = acc[mt][nt][3];
        }
    }
    __syncthreads();

    int v0g = blockIdx.x * 128;
    int t = k + 1;
    int b = tid >> 2, q = tid & 3;
    float* orow = out + ((size_t)b * Sn + t) * Vn + v0g + q * 32;
    float bv = -3.4e38f; int bi = 0x7fffffff;
    #pragma unroll
    for (int g8 = 0; g8 < 8; g8++) {
        float4 r;
        float* sp = &s_out[b][q * 32 + g8 * 4];
        const float* bp = fc_b + v0g + q * 32 + g8 * 4;
        r.x = sp[0] + bp[0];
        r.y = sp[1] + bp[1];
        r.z = sp[2] + bp[2];
        r.w = sp[3] + bp[3];
        *(float4*)(orow + g8 * 4) = r;
        int vb = v0g + q * 32 + g8 * 4;
        if (r.x > bv) { bv = r.x; bi = vb; }
        if (r.y > bv) { bv = r.y; bi = vb + 1; }
        if (r.z > bv) { bv = r.z; bi = vb + 2; }
        if (r.w > bv) { bv = r.w; bi = vb + 3; }
    }
    #pragma unroll
    for (int off = 2; off > 0; off >>= 1) {
        float ov = __shfl_down_sync(0xffffffffu, bv, off, 4);
        int   oi = __shfl_down_sync(0xffffffffu, bi, off, 4);
        if (ov > bv || (ov == bv && oi < bi)) { bv = ov; bi = oi; }
    }
    if (q == 0) {
        g_pval[b * NVB + blockIdx.x] = bv;
        g_pidx[b * NVB + blockIdx.x] = bi;
    }
}

// ---------------- launch ------------------------------------------------------
extern "C" void kernel_launch(void* const* d_in, const int* in_sizes, int n_in,
                              void* d_out, int out_size) {
    (void)in_sizes; (void)n_in; (void)out_size;
    const float*         enc  = (const float*)d_in[0];
    const int*           caps = (const int*)d_in[1];
    const unsigned char* tf   = (const unsigned char*)d_in[2];
    const float*         emb  = (const float*)d_in[3];
    const float*         W_ih = (const float*)d_in[4];
    const float*         W_hh = (const float*)d_in[5];
    const float*         b_ih = (const float*)d_in[6];
    const float*         b_hh = (const float*)d_in[7];
    const float*         fc_w = (const float*)d_in[8];
    const float*         fc_b = (const float*)d_in[9];
    float* out = (float*)d_out;

    init_kernel<<<512, 256>>>(tf, out);
    convert_w_kernel<<<(Vn * Hn + 255) / 256, 256>>>(fc_w);
    convert_wg_kernel<<<(2048 * 768 + 255) / 256, 256>>>(W_ih, W_hh);
    for (int k = 0; k < 63; k++) {
        prep_kernel<<<Bn, 256>>>(k, caps, emb, enc);
        gatescell_kernel<<<16, 256>>>(k, b_ih, b_hh);
        logits_mma_kernel<<<250, 256>>>(k, fc_b, out);
    }
}

// round 11
// speedup vs baseline: 1.9939x; 1.5845x over previous
#include <cuda_runtime.h>
#include <cuda_bf16.h>
#include <math.h>
#include <stdint.h>

#define Bn 64
#define Hn 512
#define En 256
#define Vn 32000
#define Sn 64
#define NVB 250       /* Vn / 128 v-blocks in logits kernel */
#define NKT 32        /* logits k-tiles of 16 (Hn/16) */
#define GKT 48        /* gates  k-tiles of 16 ((En+Hn)/16) */
#define GSL 6         /* gates k-slices */
#define GKS 8         /* k-tiles per slice */

// ---------------- persistent device state (no cudaMalloc allowed) ------------
__device__ float g_c[Bn * Hn];
__device__ float g_gates[16 * 128 * Bn];   // [bid][row_local][b] fp32 partials
__device__ int   g_cnt[16];                // split-K completion counters
__device__ float g_pval[Bn * NVB];
__device__ int   g_pidx[Bn * NVB];
__device__ int   g_tf[Sn];

// logits W fragments: [mtile(2000)][ktile(32)][lane(32)][8 bf16]
__device__ __nv_bfloat16 g_wfrag_hi[(size_t)Vn * Hn];
__device__ __nv_bfloat16 g_wfrag_lo[(size_t)Vn * Hn];
// gates W fragments: [cta(16)*8 + mtile][ktile(48)][lane(32)][8 bf16]
__device__ __nv_bfloat16 g_wg_hi[(size_t)128 * GKT * 32 * 8];
__device__ __nv_bfloat16 g_wg_lo[(size_t)128 * GKT * 32 * 8];
// h B-fragments, double buffered: [buf][ntile(8)][ktile(32)][lane(32)][4 bf16]
__device__ __nv_bfloat16 g_hfrag_hi[2][Bn * Hn];
__device__ __nv_bfloat16 g_hfrag_lo[2][Bn * Hn];
// x B-fragments: [ntile(8)][ktile(16)][lane(32)][4 bf16]
__device__ __nv_bfloat16 g_xfrag_hi[Bn * En];
__device__ __nv_bfloat16 g_xfrag_lo[Bn * En];

__device__ __forceinline__ float sigmoidf_(float x) {
    return 1.0f / (1.0f + expf(-x));
}

__device__ __forceinline__ void mma16816(float* c, const uint4& a, const uint2& b) {
    asm volatile(
        "mma.sync.aligned.m16n8k16.row.col.f32.bf16.bf16.f32 "
        "{%0,%1,%2,%3}, {%4,%5,%6,%7}, {%8,%9}, {%0,%1,%2,%3};"
        : "+f"(c[0]), "+f"(c[1]), "+f"(c[2]), "+f"(c[3])
        : "r"(a.x), "r"(a.y), "r"(a.z), "r"(a.w), "r"(b.x), "r"(b.y));
}

// ---------------- one-time conversions ---------------------------------------
__global__ void convert_w_kernel(const float* __restrict__ fc_w) {
    size_t idx = (size_t)blockIdx.x * blockDim.x + threadIdx.x;
    if (idx >= (size_t)Vn * Hn) return;
    int v = (int)(idx >> 9);
    int kg = (int)(idx & 511);
    float w = fc_w[idx];
    __nv_bfloat16 hi = __float2bfloat16(w);
    __nv_bfloat16 lo = __float2bfloat16(w - __bfloat162float(hi));
    int mtile = v >> 4, r = v & 15;
    int ktile = kg >> 4, c = kg & 15;
    int lane = (r & 7) * 4 + ((c & 7) >> 1);
    int reg  = (r >> 3) + 2 * (c >> 3);
    int pos  = c & 1;
    size_t off = ((size_t)(mtile * NKT + ktile) * 32 + lane) * 8 + reg * 2 + pos;
    g_wfrag_hi[off] = hi;
    g_wfrag_lo[off] = lo;
}

__global__ void convert_wg_kernel(const float* __restrict__ W_ih,
                                  const float* __restrict__ W_hh) {
    size_t idx = (size_t)blockIdx.x * blockDim.x + threadIdx.x;
    if (idx >= (size_t)2048 * 768) return;
    int R = (int)(idx / 768);
    int kc = (int)(idx % 768);
    float w = (kc < En) ? W_ih[(size_t)R * En + kc]
                        : W_hh[(size_t)R * Hn + (kc - En)];
    __nv_bfloat16 hi = __float2bfloat16(w);
    __nv_bfloat16 lo = __float2bfloat16(w - __bfloat162float(hi));
    int gate = R >> 9, j = R & 511;
    int bid = j >> 5;
    int rloc = gate * 32 + (j & 31);        // 0..127
    int mtile = bid * 8 + (rloc >> 4);
    int r16 = rloc & 15;
    int ktile = kc >> 4, c = kc & 15;
    int lane = (r16 & 7) * 4 + ((c & 7) >> 1);
    int reg  = (r16 >> 3) + 2 * (c >> 3);
    int pos  = c & 1;
    size_t off = ((size_t)(mtile * GKT + ktile) * 32 + lane) * 8 + reg * 2 + pos;
    g_wg_hi[off] = hi;
    g_wg_lo[off] = lo;
}

// ---------------- init: decode use_tf, zero gates/counters/out[:,0,:] --------
__global__ void init_kernel(const unsigned char* tf_raw, float* out) {
    if (blockIdx.x == 0) {
        __shared__ int mode;
        if (threadIdx.x == 0) {
            int gt1 = 0, odd1 = 0;
            for (int i = 0; i < Sn; i++) {
                unsigned char v = tf_raw[i];
                if (v > 1) gt1 = 1;
                if (v == 1 && (i & 3)) odd1 = 1;
            }
            mode = gt1 ? 1 : (odd1 ? 0 : 1);
        }
        __syncthreads();
        if (threadIdx.x < Sn) {
            int t = threadIdx.x;
            int val;
            if (mode == 0) val = (tf_raw[t] != 0);
            else           val = (((const unsigned int*)tf_raw)[t] != 0u);
            g_tf[t] = val;
        }
        if (threadIdx.x < 16) g_cnt[threadIdx.x] = 0;
    }
    for (int i = blockIdx.x * blockDim.x + threadIdx.x; i < 16 * 128 * Bn;
         i += gridDim.x * blockDim.x)
        g_gates[i] = 0.0f;
    for (int i = blockIdx.x * blockDim.x + threadIdx.x; i < Bn * Vn;
         i += gridDim.x * blockDim.x) {
        int b = i / Vn, v = i - b * Vn;
        out[(size_t)b * Sn * Vn + v] = 0.0f;
    }
}

// ---------------- prep: grid 64 (one CTA per batch lane) ----------------------
__global__ __launch_bounds__(256) void prep_kernel(
    int k, const int* __restrict__ captions, const float* __restrict__ emb,
    const float* __restrict__ enc)
{
    __shared__ float sval[8];
    __shared__ int   sidx[8];
    __shared__ int   tok_sh;

    int b = blockIdx.x;
    int tid = threadIdx.x;
    int lane = tid & 31, warp = tid >> 5;

    if (k == 0) {
        if (tid == 0) tok_sh = captions[b * Sn + 0];
    } else {
        float bv = -3.4e38f; int bi = 0x7fffffff;
        if (tid < NVB) { bv = g_pval[b * NVB + tid]; bi = g_pidx[b * NVB + tid]; }
        #pragma unroll
        for (int off = 16; off > 0; off >>= 1) {
            float ov = __shfl_down_sync(0xffffffffu, bv, off);
            int   oi = __shfl_down_sync(0xffffffffu, bi, off);
            if (ov > bv || (ov == bv && oi < bi)) { bv = ov; bi = oi; }
        }
        if (lane == 0) { sval[warp] = bv; sidx[warp] = bi; }
        __syncthreads();
        if (tid == 0) {
            bv = sval[0]; bi = sidx[0];
            #pragma unroll
            for (int w2 = 1; w2 < 8; w2++) {
                float ov = sval[w2]; int oi = sidx[w2];
                if (ov > bv || (ov == bv && oi < bi)) { bv = ov; bi = oi; }
            }
            tok_sh = g_tf[k] ? captions[b * Sn + k] : bi;
        }
    }
    __syncthreads();

    int tok = tok_sh;
    {
        int kg = tid;
        float x = (tok == 0) ? 0.0f : emb[(size_t)tok * En + kg];
        __nv_bfloat16 hi = __float2bfloat16(x);
        __nv_bfloat16 lo = __float2bfloat16(x - __bfloat162float(hi));
        int ntile = b >> 3, n = b & 7;
        int ktile = kg >> 4, c = kg & 15;
        int lane2 = n * 4 + ((c & 7) >> 1);
        int reg  = c >> 3, pos = c & 1;
        uint32_t off = ((uint32_t)(ntile * 16 + ktile) * 32 + lane2) * 4 + reg * 2 + pos;
        g_xfrag_hi[off] = hi;
        g_xfrag_lo[off] = lo;
    }

    if (k == 0) {
        #pragma unroll
        for (int q = 0; q < 2; q++) {
            int j = tid + q * 256;
            float h = enc[b * Hn + j];
            __nv_bfloat16 hi = __float2bfloat16(h);
            __nv_bfloat16 lo = __float2bfloat16(h - __bfloat162float(hi));
            int ntile = b >> 3, n = b & 7;
            int ktile = j >> 4, c = j & 15;
            int lane2 = n * 4 + ((c & 7) >> 1);
            int reg  = c >> 3, pos = c & 1;
            uint32_t off = ((uint32_t)(ntile * NKT + ktile) * 32 + lane2) * 4 + reg * 2 + pos;
            g_hfrag_hi[0][off] = hi;
            g_hfrag_lo[0][off] = lo;
        }
    }
}

// ---------------- gates MMA split-K + last-CTA cell epilogue ------------------
// grid (16, 6) x 256. CTA (bid, s): rows [bid*32 x 4 gates], k-tiles [s*8, +8).
__global__ __launch_bounds__(256) void gatescell_kernel(
    int k, const float* __restrict__ b_ih, const float* __restrict__ b_hh)
{
    __shared__ int is_last;

    int tid = threadIdx.x;
    int wid = tid >> 5, lane = tid & 31;
    int mw = wid & 3, nw = wid >> 2;
    int gid = lane >> 2, tig = lane & 3;
    int bid = blockIdx.x;
    int slice = blockIdx.y;
    int rb = k & 1, wb = (k + 1) & 1;

    const uint4* wh4 = (const uint4*)g_wg_hi;
    const uint4* wl4 = (const uint4*)g_wg_lo;
    const uint2* xh2 = (const uint2*)g_xfrag_hi;
    const uint2* xl2 = (const uint2*)g_xfrag_lo;
    const uint2* hh2 = (const uint2*)g_hfrag_hi[rb];
    const uint2* hl2 = (const uint2*)g_hfrag_lo[rb];

    float acc[2][4][4];
    #pragma unroll
    for (int mt = 0; mt < 2; mt++)
        #pragma unroll
        for (int nt = 0; nt < 4; nt++)
            #pragma unroll
            for (int i = 0; i < 4; i++) acc[mt][nt][i] = 0.0f;

    int mt_g0 = bid * 8 + mw * 2;
    int kt0 = slice * GKS;
    bool xslice = (slice < 2);

    #pragma unroll
    for (int kq = 0; kq < GKS; kq++) {
        int kt = kt0 + kq;
        uint4 ahi[2], alo[2];
        #pragma unroll
        for (int mt = 0; mt < 2; mt++) {
            size_t base = ((size_t)(mt_g0 + mt) * GKT + kt) * 32 + lane;
            ahi[mt] = wh4[base];
            alo[mt] = wl4[base];
        }
        #pragma unroll
        for (int nt = 0; nt < 4; nt++) {
            int nt_g = nw * 4 + nt;
            uint2 bhi, blo;
            if (xslice) {
                uint32_t bbase = (uint32_t)(nt_g * 16 + kt) * 32 + lane;
                bhi = xh2[bbase]; blo = xl2[bbase];
            } else {
                uint32_t bbase = (uint32_t)(nt_g * NKT + (kt - 16)) * 32 + lane;
                bhi = hh2[bbase]; blo = hl2[bbase];
            }
            #pragma unroll
            for (int mt = 0; mt < 2; mt++) {
                mma16816(acc[mt][nt], ahi[mt], bhi);
                mma16816(acc[mt][nt], ahi[mt], blo);
                mma16816(acc[mt][nt], alo[mt], bhi);
            }
        }
    }

    // accumulate partials into g_gates[bid][rl][b]
    float* gbase = g_gates + bid * (128 * Bn);
    #pragma unroll
    for (int mt = 0; mt < 2; mt++) {
        int rl = mw * 32 + mt * 16 + gid;
        #pragma unroll
        for (int nt = 0; nt < 4; nt++) {
            int bl = (nw * 4 + nt) * 8 + tig * 2;
            atomicAdd(&gbase[rl * Bn + bl],           acc[mt][nt][0]);
            atomicAdd(&gbase[rl * Bn + bl + 1],       acc[mt][nt][1]);
            atomicAdd(&gbase[(rl + 8) * Bn + bl],     acc[mt][nt][2]);
            atomicAdd(&gbase[(rl + 8) * Bn + bl + 1], acc[mt][nt][3]);
        }
    }

    __threadfence();
    __syncthreads();
    if (tid == 0) {
        int prev = atomicAdd(&g_cnt[bid], 1);
        is_last = (prev == GSL - 1);
    }
    __syncthreads();
    if (!is_last) return;

    // last CTA for this bid: cell update for j in [bid*32, +32), all b
    #pragma unroll
    for (int it = 0; it < 8; it++) {
        int e = tid + it * 256;
        int jl = e >> 6, b = e & 63;
        int j = bid * 32 + jl;

        float gi = gbase[jl * Bn + b]         + b_ih[j]          + b_hh[j];
        float gf = gbase[(32 + jl) * Bn + b]  + b_ih[Hn + j]     + b_hh[Hn + j];
        float gg = gbase[(64 + jl) * Bn + b]  + b_ih[2 * Hn + j] + b_hh[2 * Hn + j];
        float go = gbase[(96 + jl) * Bn + b]  + b_ih[3 * Hn + j] + b_hh[3 * Hn + j];

        float c_old = (k == 0) ? 0.0f : g_c[b * Hn + j];
        float c = sigmoidf_(gf) * c_old + sigmoidf_(gi) * tanhf(gg);
        float h = sigmoidf_(go) * tanhf(c);
        g_c[b * Hn + j] = c;

        __nv_bfloat16 hi = __float2bfloat16(h);
        __nv_bfloat16 lo = __float2bfloat16(h - __bfloat162float(hi));
        int ntile = b >> 3, n = b & 7;
        int ktile = j >> 4, c2 = j & 15;
        int lane2 = n * 4 + ((c2 & 7) >> 1);
        int reg  = c2 >> 3, pos = c2 & 1;
        uint32_t off = ((uint32_t)(ntile * NKT + ktile) * 32 + lane2) * 4 + reg * 2 + pos;
        g_hfrag_hi[wb][off] = hi;
        g_hfrag_lo[wb][off] = lo;
    }
    __syncthreads();
    // re-zero this bid's gates slab and reset counter for next step
    float4 z4 = make_float4(0.f, 0.f, 0.f, 0.f);
    float4* gz = (float4*)gbase;
    #pragma unroll
    for (int it = 0; it < 8; it++)
        gz[tid + it * 256] = z4;
    if (tid == 0) g_cnt[bid] = 0;
}

// ---------------- logits GEMM via mma.sync bf16 (3-term split) ---------------
__global__ __launch_bounds__(256) void logits_mma_kernel(
    int k, const float* __restrict__ fc_b, float* __restrict__ out)
{
    __shared__ float s_out[Bn][132];

    int tid = threadIdx.x;
    int wid = tid >> 5, lane = tid & 31;
    int mw = wid & 3, nw = wid >> 2;
    int gid = lane >> 2, tig = lane & 3;
    int wb = (k + 1) & 1;

    const uint4* wh4 = (const uint4*)g_wfrag_hi;
    const uint4* wl4 = (const uint4*)g_wfrag_lo;
    const uint2* hh2 = (const uint2*)g_hfrag_hi[wb];
    const uint2* hl2 = (const uint2*)g_hfrag_lo[wb];

    int mt_g0 = blockIdx.x * 8 + mw * 2;

    float acc[2][4][4];
    #pragma unroll
    for (int mt = 0; mt < 2; mt++)
        #pragma unroll
        for (int nt = 0; nt < 4; nt++)
            #pragma unroll
            for (int i = 0; i < 4; i++) acc[mt][nt][i] = 0.0f;

    for (int kt = 0; kt < NKT; kt++) {
        uint4 ahi[2], alo[2];
        #pragma unroll
        for (int mt = 0; mt < 2; mt++) {
            size_t base = ((size_t)(mt_g0 + mt) * NKT + kt) * 32 + lane;
            ahi[mt] = wh4[base];
            alo[mt] = wl4[base];
        }
        #pragma unroll
        for (int nt = 0; nt < 4; nt++) {
            int nt_g = nw * 4 + nt;
            uint32_t bbase = (uint32_t)(nt_g * NKT + kt) * 32 + lane;
            uint2 bhi = hh2[bbase];
            uint2 blo = hl2[bbase];
            #pragma unroll
            for (int mt = 0; mt < 2; mt++) {
                mma16816(acc[mt][nt], ahi[mt], bhi);
                mma16816(acc[mt][nt], ahi[mt], blo);
                mma16816(acc[mt][nt], alo[mt], bhi);
            }
        }
    }

    #pragma unroll
    for (int mt = 0; mt < 2; mt++) {
        int vl = mw * 32 + mt * 16 + gid;
        #pragma unroll
        for (int nt = 0; nt < 4; nt++) {
            int bl = (nw * 4 + nt) * 8 + tig * 2;
            s_out[bl][vl]         = acc[mt][nt][0];
            s_out[bl + 1][vl]     = acc[mt][nt][1];
            s_out[bl][vl + 8]     = acc[mt][nt][2];
            s_out[bl + 1][vl + 8] = acc[mt][nt][3];
        }
    }
    __syncthreads();

    int v0g = blockIdx.x * 128;
    int t = k + 1;
    int b = tid >> 2, q = tid & 3;
    float* orow = out + ((size_t)b * Sn + t) * Vn + v0g + q * 32;
    float bv = -3.4e38f; int bi = 0x7fffffff;
    #pragma unroll
    for (int g8 = 0; g8 < 8; g8++) {
        float4 r;
        float* sp = &s_out[b][q * 32 + g8 * 4];
        const float* bp = fc_b + v0g + q * 32 + g8 * 4;
        r.x = sp[0] + bp[0];
        r.y = sp[1] + bp[1];
        r.z = sp[2] + bp[2];
        r.w = sp[3] + bp[3];
        *(float4*)(orow + g8 * 4) = r;
        int vb = v0g + q * 32 + g8 * 4;
        if (r.x > bv) { bv = r.x; bi = vb; }
        if (r.y > bv) { bv = r.y; bi = vb + 1; }
        if (r.z > bv) { bv = r.z; bi = vb + 2; }
        if (r.w > bv) { bv = r.w; bi = vb + 3; }
    }
    #pragma unroll
    for (int off = 2; off > 0; off >>= 1) {
        float ov = __shfl_down_sync(0xffffffffu, bv, off, 4);
        int   oi = __shfl_down_sync(0xffffffffu, bi, off, 4);
        if (ov > bv || (ov == bv && oi < bi)) { bv = ov; bi = oi; }
    }
    if (q == 0) {
        g_pval[b * NVB + blockIdx.x] = bv;
        g_pidx[b * NVB + blockIdx.x] = bi;
    }
}

// ---------------- launch ------------------------------------------------------
extern "C" void kernel_launch(void* const* d_in, const int* in_sizes, int n_in,
                              void* d_out, int out_size) {
    (void)in_sizes; (void)n_in; (void)out_size;
    const float*         enc  = (const float*)d_in[0];
    const int*           caps = (const int*)d_in[1];
    const unsigned char* tf   = (const unsigned char*)d_in[2];
    const float*         emb  = (const float*)d_in[3];
    const float*         W_ih = (const float*)d_in[4];
    const float*         W_hh = (const float*)d_in[5];
    const float*         b_ih = (const float*)d_in[6];
    const float*         b_hh = (const float*)d_in[7];
    const float*         fc_w = (const float*)d_in[8];
    const float*         fc_b = (const float*)d_in[9];
    float* out = (float*)d_out;

    init_kernel<<<512, 256>>>(tf, out);
    convert_w_kernel<<<(Vn * Hn + 255) / 256, 256>>>(fc_w);
    convert_wg_kernel<<<(2048 * 768 + 255) / 256, 256>>>(W_ih, W_hh);
    dim3 gGrid(16, GSL);
    for (int k = 0; k < 63; k++) {
        prep_kernel<<<Bn, 256>>>(k, caps, emb, enc);
        gatescell_kernel<<<gGrid, 256>>>(k, b_ih, b_hh);
        logits_mma_kernel<<<250, 256>>>(k, fc_b, out);
    }
}